// round 1
// baseline (speedup 1.0000x reference)
#include <cuda_runtime.h>
#include <math.h>

#define HIDDEN     64
#define NBASIS     10
#define SEQ        96
#define BATCH      16384
#define NPAIR      (HIDDEN * NBASIS)   // 640
#define GTAB       2048
#define WARPS_PB   16
#define TBLOCK     (WARPS_PB * 32)     // 512
#define PAIR_TILE  160                 // pairs per smem tile (4 tiles of 160)
#define I_PER_TILE 16                  // 160 pairs = 16 hidden rows

__device__ float  g_lo, g_hi;
__device__ float2 g_table[GTAB];

// ---------------------------------------------------------------------------
// Kernel 0: min/max of x[:, SEQ-1] -> exact interpolation domain
// ---------------------------------------------------------------------------
__global__ void k_minmax(const float* __restrict__ x) {
    __shared__ float smn[1024];
    __shared__ float smx[1024];
    int tid = threadIdx.x;
    float mn = 1e30f, mx = -1e30f;
    for (int j = tid; j < BATCH; j += 1024) {
        float v = x[j * SEQ + (SEQ - 1)];
        mn = fminf(mn, v);
        mx = fmaxf(mx, v);
    }
    smn[tid] = mn; smx[tid] = mx;
    __syncthreads();
    for (int s = 512; s > 0; s >>= 1) {
        if (tid < s) {
            smn[tid] = fminf(smn[tid], smn[tid + s]);
            smx[tid] = fmaxf(smx[tid], smx[tid + s]);
        }
        __syncthreads();
    }
    if (tid == 0) {
        float lo = smn[0], hi = smx[0];
        float span = hi - lo;
        if (span < 1e-3f) span = 1e-3f;   // degenerate guard
        g_lo = lo - 1e-3f;
        g_hi = lo - 1e-3f + span + 2e-3f;
    }
}

// ---------------------------------------------------------------------------
// Kernel 1: tabulate F(x_g) for G grid points. One warp per grid point.
// ---------------------------------------------------------------------------
__global__ void __launch_bounds__(TBLOCK) k_table(
    const float* __restrict__ Wx,  const float* __restrict__ ax,
    const float* __restrict__ cx,  const float* __restrict__ Wc,
    const float* __restrict__ ac,  const float* __restrict__ cc,
    const float* __restrict__ Wout)
{
    __shared__ __align__(16) float Wt[PAIR_TILE * HIDDEN];   // 40 KB tile
    __shared__ float hsh[WARPS_PB][HIDDEN];                  // 4 KB

    const int tid  = threadIdx.x;
    const int wid  = tid >> 5;
    const int lane = tid & 31;
    const int g    = blockIdx.x * WARPS_PB + wid;

    const float lo = g_lo, hi = g_hi;
    const float hstep = (hi - lo) / (float)(GTAB - 4);
    const float xg = lo + ((float)g - 1.5f) * hstep;

    // ---- basis of x: t_k (redundant per lane, trivial cost) ----
    float tk[NBASIS];
    #pragma unroll
    for (int k = 0; k < NBASIS; k++)
        tk[k] = tanhf(xg * ax[k] + cx[k]);

    // ---- hidden vector h[64]: lane handles o = lane, lane+32 ----
    float* hw = hsh[wid];
    #pragma unroll
    for (int half = 0; half < 2; half++) {
        int o = lane + half * 32;
        float s = 0.f;
        #pragma unroll
        for (int k = 0; k < NBASIS; k++)
            s += tk[k] * Wx[o * NBASIS + k];
        hw[o] = tanhf(s);
    }
    __syncwarp();

    // ---- classifier: acc over 640 (i,k) pairs, lane owns o = 2*lane, 2*lane+1
    unsigned long long accA = 0ull, accB = 0ull;   // packed f32x2 accumulators

    for (int tile = 0; tile < NPAIR / PAIR_TILE; tile++) {
        __syncthreads();   // protect Wt from previous-tile readers
        // transpose-load Wc tile: Wc[i*640 + o*10 + k] -> Wt[(local pair)*64 + o]
        const int gbase = tile * (I_PER_TILE * HIDDEN * NBASIS);  // tile*10240
        for (int idx = tid; idx < I_PER_TILE * HIDDEN * NBASIS; idx += TBLOCK) {
            int gi  = gbase + idx;
            int i   = gi / (HIDDEN * NBASIS);
            int rem = gi - i * (HIDDEN * NBASIS);
            int o   = rem / NBASIS;
            int k   = rem - o * NBASIS;
            int lp  = (i - tile * I_PER_TILE) * NBASIS + k;
            Wt[lp * HIDDEN + o] = Wc[gi];
        }
        __syncthreads();

        #pragma unroll
        for (int c = 0; c < PAIR_TILE / 32; c++) {            // 5 chunks of 32
            int gpair = tile * PAIR_TILE + c * 32 + lane;
            int i     = gpair / NBASIS;
            float p   = tanhf(hw[i] * ac[gpair] + cc[gpair]);

            #pragma unroll
            for (int j = 0; j < 32; j += 2) {
                // even j -> accA
                {
                    float pj = __shfl_sync(0xffffffffu, p, j);
                    unsigned int pb = __float_as_uint(pj);
                    unsigned long long pp, ww;
                    asm("mov.b64 %0, {%1, %1};" : "=l"(pp) : "r"(pb));
                    ww = *reinterpret_cast<const unsigned long long*>(
                             &Wt[(c * 32 + j) * HIDDEN + 2 * lane]);
                    asm("fma.rn.f32x2 %0, %1, %2, %0;" : "+l"(accA) : "l"(pp), "l"(ww));
                }
                // odd j -> accB
                {
                    float pj = __shfl_sync(0xffffffffu, p, j + 1);
                    unsigned int pb = __float_as_uint(pj);
                    unsigned long long pp, ww;
                    asm("mov.b64 %0, {%1, %1};" : "=l"(pp) : "r"(pb));
                    ww = *reinterpret_cast<const unsigned long long*>(
                             &Wt[(c * 32 + j + 1) * HIDDEN + 2 * lane]);
                    asm("fma.rn.f32x2 %0, %1, %2, %0;" : "+l"(accB) : "l"(pp), "l"(ww));
                }
            }
        }
    }

    // unpack + combine
    unsigned int a0b, a1b, b0b, b1b;
    asm("mov.b64 {%0, %1}, %2;" : "=r"(a0b), "=r"(a1b) : "l"(accA));
    asm("mov.b64 {%0, %1}, %2;" : "=r"(b0b), "=r"(b1b) : "l"(accB));
    float s0 = __uint_as_float(a0b) + __uint_as_float(b0b);
    float s1 = __uint_as_float(a1b) + __uint_as_float(b1b);

    float phi0 = tanhf(s0);
    float phi1 = tanhf(s1);
    int o0 = 2 * lane, o1 = 2 * lane + 1;
    float c0 = phi0 * Wout[o0 * 2 + 0] + phi1 * Wout[o1 * 2 + 0];
    float c1 = phi0 * Wout[o0 * 2 + 1] + phi1 * Wout[o1 * 2 + 1];

    #pragma unroll
    for (int s = 16; s > 0; s >>= 1) {
        c0 += __shfl_xor_sync(0xffffffffu, c0, s);
        c1 += __shfl_xor_sync(0xffffffffu, c1, s);
    }
    if (lane == 0)
        g_table[g] = make_float2(c0, c1);
}

// ---------------------------------------------------------------------------
// Kernel 2: per-batch 4-point cubic Lagrange interpolation
// ---------------------------------------------------------------------------
__global__ void k_apply(const float* __restrict__ x, float* __restrict__ out) {
    int b = blockIdx.x * blockDim.x + threadIdx.x;
    if (b >= BATCH) return;
    float xv = x[b * SEQ + (SEQ - 1)];
    float lo = g_lo, hi = g_hi;
    float hstep = (hi - lo) / (float)(GTAB - 4);
    float t = (xv - lo) / hstep + 1.5f;
    int i0 = (int)floorf(t);
    i0 = max(1, min(GTAB - 3, i0));
    float u = t - (float)i0;

    float um1 = u - 1.f, um2 = u - 2.f, up1 = u + 1.f;
    float wA = -u * um1 * um2 * (1.f / 6.f);
    float wB =  up1 * um1 * um2 * 0.5f;
    float wC = -up1 * u * um2 * 0.5f;
    float wD =  up1 * u * um1 * (1.f / 6.f);

    float2 fA = g_table[i0 - 1];
    float2 fB = g_table[i0];
    float2 fC = g_table[i0 + 1];
    float2 fD = g_table[i0 + 2];

    float o0 = wA * fA.x + wB * fB.x + wC * fC.x + wD * fD.x;
    float o1 = wA * fA.y + wB * fB.y + wC * fC.y + wD * fD.y;
    reinterpret_cast<float2*>(out)[b] = make_float2(o0, o1);
}

// ---------------------------------------------------------------------------
extern "C" void kernel_launch(void* const* d_in, const int* in_sizes, int n_in,
                              void* d_out, int out_size) {
    const float* x    = (const float*)d_in[0];
    const float* Wx   = (const float*)d_in[1];
    const float* ax   = (const float*)d_in[2];
    const float* cx   = (const float*)d_in[3];
    // d_in[4..6] = Wh, ah, ch -- mathematically unused by the reference
    const float* Wc   = (const float*)d_in[7];
    const float* ac   = (const float*)d_in[8];
    const float* cc   = (const float*)d_in[9];
    const float* Wout = (const float*)d_in[10];

    k_minmax<<<1, 1024>>>(x);
    k_table<<<GTAB / WARPS_PB, TBLOCK>>>(Wx, ax, cx, Wc, ac, cc, Wout);
    k_apply<<<(BATCH + 255) / 256, 256>>>(x, (float*)d_out);
}

// round 2
// speedup vs baseline: 1.1943x; 1.1943x over previous
#include <cuda_runtime.h>
#include <math.h>

#define HIDDEN     64
#define NBASIS     10
#define SEQ        96
#define BATCH      16384
#define NPAIR      (HIDDEN * NBASIS)   // 640
#define GTAB       512
#define WARPS_PB   4
#define TBLOCK     (WARPS_PB * 32)     // 128
#define NPART      64                  // minmax partial blocks

__device__ float  g_pmin[NPART], g_pmax[NPART];
__device__ float  g_Wct[NPAIR * HIDDEN];   // transposed Wc: [pair][o], 160KB
__device__ float2 g_table[GTAB];

// ---------------------------------------------------------------------------
// Kernel 0: fused (a) per-block min/max partials of x[:,SEQ-1]
//           (b) transpose Wc[i][o][k] -> g_Wct[(i*10+k)*64 + o]
// grid = 64 blocks x 256 threads  (64*256 == BATCH, one x-load per thread)
// ---------------------------------------------------------------------------
__global__ void __launch_bounds__(256) k_pre(const float* __restrict__ x,
                                             const float* __restrict__ Wc) {
    __shared__ float smn[256], smx[256];
    const int tid = threadIdx.x;
    const int gt  = blockIdx.x * 256 + tid;

    // (a) min/max
    float v = x[gt * SEQ + (SEQ - 1)];
    smn[tid] = v; smx[tid] = v;
    __syncthreads();
    #pragma unroll
    for (int s = 128; s > 0; s >>= 1) {
        if (tid < s) {
            smn[tid] = fminf(smn[tid], smn[tid + s]);
            smx[tid] = fmaxf(smx[tid], smx[tid + s]);
        }
        __syncthreads();
    }
    if (tid == 0) {
        g_pmin[blockIdx.x] = smn[0];
        g_pmax[blockIdx.x] = smx[0];
    }

    // (b) transpose Wc: 40960 elements over 16384 threads (2.5 per thread)
    for (int idx = gt; idx < NPAIR * HIDDEN; idx += NPART * 256) {
        int p = idx >> 6;          // pair = i*10 + k
        int o = idx & 63;
        int i = p / NBASIS;
        int k = p - i * NBASIS;
        g_Wct[p * HIDDEN + o] = Wc[i * (HIDDEN * NBASIS) + o * NBASIS + k];
    }
}

// ---------------------------------------------------------------------------
// Kernel 1: tabulate F at GTAB grid points. One warp per grid point.
// grid = GTAB/WARPS_PB = 128 blocks x 128 threads
// ---------------------------------------------------------------------------
__global__ void __launch_bounds__(TBLOCK) k_table(
    const float* __restrict__ Wx,  const float* __restrict__ ax,
    const float* __restrict__ cx,  const float* __restrict__ ac,
    const float* __restrict__ cc,  const float* __restrict__ Wout)
{
    __shared__ float s_red[2][NPART];
    __shared__ float s_range[2];                 // lo, hstep
    __shared__ float hsh[WARPS_PB][HIDDEN];      // 1 KB
    __shared__ float psh[WARPS_PB][NPAIR];       // 10 KB

    const int tid  = threadIdx.x;
    const int wid  = tid >> 5;
    const int lane = tid & 31;
    const int g    = blockIdx.x * WARPS_PB + wid;

    // ---- stage 0: reduce the 64 min/max partials (redundant per block) ----
    if (tid < NPART) {
        s_red[0][tid] = g_pmin[tid];
        s_red[1][tid] = g_pmax[tid];
    }
    __syncthreads();
    if (tid < 32) {
        float mn = fminf(s_red[0][tid], s_red[0][tid + 32]);
        float mx = fmaxf(s_red[1][tid], s_red[1][tid + 32]);
        #pragma unroll
        for (int s = 16; s > 0; s >>= 1) {
            mn = fminf(mn, __shfl_xor_sync(0xffffffffu, mn, s));
            mx = fmaxf(mx, __shfl_xor_sync(0xffffffffu, mx, s));
        }
        if (tid == 0) {
            float span = mx - mn;
            if (span < 1e-3f) span = 1e-3f;
            float lo = mn - 1e-3f;
            s_range[0] = lo;
            s_range[1] = (span + 2e-3f) / (float)(GTAB - 4);
        }
    }
    __syncthreads();

    const float lo    = s_range[0];
    const float hstep = s_range[1];
    const float xg    = lo + ((float)g - 1.5f) * hstep;

    // ---- stage 1: h[64] for this grid point ----
    float tk[NBASIS];
    #pragma unroll
    for (int k = 0; k < NBASIS; k++)
        tk[k] = tanhf(xg * ax[k] + cx[k]);

    float* hw = hsh[wid];
    #pragma unroll
    for (int half = 0; half < 2; half++) {
        int o = lane + half * 32;
        float s = 0.f;
        #pragma unroll
        for (int k = 0; k < NBASIS; k++)
            s += tk[k] * Wx[o * NBASIS + k];
        hw[o] = tanhf(s);
    }
    __syncwarp();

    // ---- stage 2: p[640] = tanh(h[i]*ac + cc) into shared ----
    float* pw = psh[wid];
    #pragma unroll
    for (int j0 = 0; j0 < NPAIR / 32; j0++) {
        int pair = j0 * 32 + lane;
        int i    = pair / NBASIS;
        pw[pair] = tanhf(hw[i] * ac[pair] + cc[pair]);
    }
    __syncwarp();

    // ---- stage 3: acc[o=2*lane, 2*lane+1] over 640 pairs ----
    unsigned long long accA = 0ull, accB = 0ull;
    const unsigned long long* wbase =
        reinterpret_cast<const unsigned long long*>(g_Wct) + lane;  // +pair*32

    #pragma unroll 16
    for (int pair = 0; pair < NPAIR; pair += 2) {
        {
            float pj = pw[pair];                       // LDS broadcast
            unsigned int pb = __float_as_uint(pj);
            unsigned long long pp, ww;
            asm("mov.b64 %0, {%1, %1};" : "=l"(pp) : "r"(pb));
            ww = __ldg(wbase + (size_t)pair * 32);
            asm("fma.rn.f32x2 %0, %1, %2, %0;" : "+l"(accA) : "l"(pp), "l"(ww));
        }
        {
            float pj = pw[pair + 1];
            unsigned int pb = __float_as_uint(pj);
            unsigned long long pp, ww;
            asm("mov.b64 %0, {%1, %1};" : "=l"(pp) : "r"(pb));
            ww = __ldg(wbase + (size_t)(pair + 1) * 32);
            asm("fma.rn.f32x2 %0, %1, %2, %0;" : "+l"(accB) : "l"(pp), "l"(ww));
        }
    }

    unsigned int a0b, a1b, b0b, b1b;
    asm("mov.b64 {%0, %1}, %2;" : "=r"(a0b), "=r"(a1b) : "l"(accA));
    asm("mov.b64 {%0, %1}, %2;" : "=r"(b0b), "=r"(b1b) : "l"(accB));
    float s0 = __uint_as_float(a0b) + __uint_as_float(b0b);
    float s1 = __uint_as_float(a1b) + __uint_as_float(b1b);

    float phi0 = tanhf(s0);
    float phi1 = tanhf(s1);
    int o0 = 2 * lane, o1 = 2 * lane + 1;
    float c0 = phi0 * Wout[o0 * 2 + 0] + phi1 * Wout[o1 * 2 + 0];
    float c1 = phi0 * Wout[o0 * 2 + 1] + phi1 * Wout[o1 * 2 + 1];

    #pragma unroll
    for (int s = 16; s > 0; s >>= 1) {
        c0 += __shfl_xor_sync(0xffffffffu, c0, s);
        c1 += __shfl_xor_sync(0xffffffffu, c1, s);
    }
    if (lane == 0)
        g_table[g] = make_float2(c0, c1);
}

// ---------------------------------------------------------------------------
// Kernel 2: per-batch 4-point cubic Lagrange interpolation
// ---------------------------------------------------------------------------
__global__ void __launch_bounds__(256) k_apply(const float* __restrict__ x,
                                               float* __restrict__ out) {
    int b = blockIdx.x * blockDim.x + threadIdx.x;
    float xv = x[b * SEQ + (SEQ - 1)];
    // reconstruct lo/hstep from partials (redundant per thread is wasteful;
    // reduce once per block into shared)
    __shared__ float s_lo, s_h;
    if (threadIdx.x < 32) {
        float mn = fminf(g_pmin[threadIdx.x], g_pmin[threadIdx.x + 32]);
        float mx = fmaxf(g_pmax[threadIdx.x], g_pmax[threadIdx.x + 32]);
        #pragma unroll
        for (int s = 16; s > 0; s >>= 1) {
            mn = fminf(mn, __shfl_xor_sync(0xffffffffu, mn, s));
            mx = fmaxf(mx, __shfl_xor_sync(0xffffffffu, mx, s));
        }
        if (threadIdx.x == 0) {
            float span = mx - mn;
            if (span < 1e-3f) span = 1e-3f;
            s_lo = mn - 1e-3f;
            s_h  = (span + 2e-3f) / (float)(GTAB - 4);
        }
    }
    __syncthreads();

    float t = (xv - s_lo) / s_h + 1.5f;
    int i0 = (int)floorf(t);
    i0 = max(1, min(GTAB - 3, i0));
    float u = t - (float)i0;

    float um1 = u - 1.f, um2 = u - 2.f, up1 = u + 1.f;
    float wA = -u * um1 * um2 * (1.f / 6.f);
    float wB =  up1 * um1 * um2 * 0.5f;
    float wC = -up1 * u * um2 * 0.5f;
    float wD =  up1 * u * um1 * (1.f / 6.f);

    float2 fA = g_table[i0 - 1];
    float2 fB = g_table[i0];
    float2 fC = g_table[i0 + 1];
    float2 fD = g_table[i0 + 2];

    float o0 = wA * fA.x + wB * fB.x + wC * fC.x + wD * fD.x;
    float o1 = wA * fA.y + wB * fB.y + wC * fC.y + wD * fD.y;
    reinterpret_cast<float2*>(out)[b] = make_float2(o0, o1);
}

// ---------------------------------------------------------------------------
extern "C" void kernel_launch(void* const* d_in, const int* in_sizes, int n_in,
                              void* d_out, int out_size) {
    const float* x    = (const float*)d_in[0];
    const float* Wx   = (const float*)d_in[1];
    const float* ax   = (const float*)d_in[2];
    const float* cx   = (const float*)d_in[3];
    // d_in[4..6] = Wh, ah, ch -- mathematically unused by the reference
    const float* Wc   = (const float*)d_in[7];
    const float* ac   = (const float*)d_in[8];
    const float* cc   = (const float*)d_in[9];
    const float* Wout = (const float*)d_in[10];

    k_pre  <<<NPART, 256>>>(x, Wc);
    k_table<<<GTAB / WARPS_PB, TBLOCK>>>(Wx, ax, cx, ac, cc, Wout);
    k_apply<<<BATCH / 256, 256>>>(x, (float*)d_out);
}

// round 3
// speedup vs baseline: 2.0994x; 1.7578x over previous
#include <cuda_runtime.h>
#include <math.h>

#define HIDDEN     64
#define NBASIS     10
#define SEQ        96
#define BATCH      16384
#define NPAIR      (HIDDEN * NBASIS)   // 640
#define GTAB       128
#define NPART      128                 // minmax partial blocks
#define PAIRS_PW   (NPAIR / 4)         // 160 pairs per warp in k_table

__device__ float  g_pmin[NPART], g_pmax[NPART];
__device__ float  g_xlast[BATCH];          // compact copy of x[:, SEQ-1]
__device__ float  g_Wct[NPAIR * HIDDEN];   // transposed Wc: [pair][o], 160KB
__device__ float2 g_table[GTAB];

// ---------------------------------------------------------------------------
// Kernel 0: (a) stash x[:,95] compactly + per-block min/max partials
//           (b) transpose Wc[i][o][k] -> g_Wct[(i*10+k)*64 + o]
// grid = 128 blocks x 128 threads (one x element per thread)
// ---------------------------------------------------------------------------
__global__ void __launch_bounds__(128) k_pre(const float* __restrict__ x,
                                             const float* __restrict__ Wc) {
    __shared__ float smn[4], smx[4];
    const int tid = threadIdx.x;
    const int gt  = blockIdx.x * 128 + tid;
    const int wid = tid >> 5, lane = tid & 31;

    float v = x[gt * SEQ + (SEQ - 1)];
    g_xlast[gt] = v;

    float mn = v, mx = v;
    #pragma unroll
    for (int s = 16; s > 0; s >>= 1) {
        mn = fminf(mn, __shfl_xor_sync(0xffffffffu, mn, s));
        mx = fmaxf(mx, __shfl_xor_sync(0xffffffffu, mx, s));
    }
    if (lane == 0) { smn[wid] = mn; smx[wid] = mx; }
    __syncthreads();
    if (tid == 0) {
        float bmn = fminf(fminf(smn[0], smn[1]), fminf(smn[2], smn[3]));
        float bmx = fmaxf(fmaxf(smx[0], smx[1]), fmaxf(smx[2], smx[3]));
        g_pmin[blockIdx.x] = bmn;
        g_pmax[blockIdx.x] = bmx;
    }

    // transpose Wc: 40960 elements over 16384 threads
    for (int idx = gt; idx < NPAIR * HIDDEN; idx += NPART * 128) {
        int p = idx >> 6;          // pair = i*10 + k
        int o = idx & 63;
        int i = p / NBASIS;
        int k = p - i * NBASIS;
        g_Wct[p * HIDDEN + o] = Wc[i * (HIDDEN * NBASIS) + o * NBASIS + k];
    }
}

// ---------------------------------------------------------------------------
// shared helper: reduce the 128 min/max partials with the first warp
// ---------------------------------------------------------------------------
__device__ __forceinline__ void reduce_range(int tid, float* s_lo, float* s_h) {
    if (tid < 32) {
        float mn = fminf(fminf(g_pmin[tid], g_pmin[tid + 32]),
                         fminf(g_pmin[tid + 64], g_pmin[tid + 96]));
        float mx = fmaxf(fmaxf(g_pmax[tid], g_pmax[tid + 32]),
                         fmaxf(g_pmax[tid + 64], g_pmax[tid + 96]));
        #pragma unroll
        for (int s = 16; s > 0; s >>= 1) {
            mn = fminf(mn, __shfl_xor_sync(0xffffffffu, mn, s));
            mx = fmaxf(mx, __shfl_xor_sync(0xffffffffu, mx, s));
        }
        if (tid == 0) {
            float span = mx - mn;
            if (span < 1e-3f) span = 1e-3f;
            *s_lo = mn - 1e-3f;
            *s_h  = (span + 2e-3f) / (float)(GTAB - 4);
        }
    }
}

// ---------------------------------------------------------------------------
// Kernel 1: tabulate F at GTAB grid points. One BLOCK (4 warps) per point.
// grid = GTAB blocks x 128 threads
// ---------------------------------------------------------------------------
__global__ void __launch_bounds__(128) k_table(
    const float* __restrict__ Wx,  const float* __restrict__ ax,
    const float* __restrict__ cx,  const float* __restrict__ ac,
    const float* __restrict__ cc,  const float* __restrict__ Wout)
{
    __shared__ float s_lo, s_h;
    __shared__ float hsh[HIDDEN];                       // 256 B
    __shared__ float psh[NPAIR];                        // 2.5 KB
    __shared__ unsigned long long sacc[4][32];          // 1 KB

    const int tid  = threadIdx.x;
    const int wid  = tid >> 5;
    const int lane = tid & 31;
    const int g    = blockIdx.x;

    reduce_range(tid, &s_lo, &s_h);
    __syncthreads();

    const float xg = s_lo + ((float)g - 1.5f) * s_h;

    // ---- h[64]: threads 0..63 each compute one output ----
    if (tid < HIDDEN) {
        float s = 0.f;
        #pragma unroll
        for (int k = 0; k < NBASIS; k++) {
            float t = tanhf(xg * ax[k] + cx[k]);
            s += t * Wx[tid * NBASIS + k];
        }
        hsh[tid] = tanhf(s);
    }
    __syncthreads();

    // ---- p[640] = tanh(h[i]*ac + cc): 5 per thread ----
    #pragma unroll
    for (int j = 0; j < NPAIR / 128; j++) {
        int pair = j * 128 + tid;
        int i    = pair / NBASIS;
        psh[pair] = tanhf(hsh[i] * ac[pair] + cc[pair]);
    }
    __syncthreads();

    // ---- warp w accumulates pairs [w*160, w*160+160) for o = 2*lane,2*lane+1
    unsigned long long accA = 0ull, accB = 0ull;
    const int pair0 = wid * PAIRS_PW;
    const unsigned long long* wbase =
        reinterpret_cast<const unsigned long long*>(g_Wct) + lane;

    #pragma unroll 8
    for (int pp = 0; pp < PAIRS_PW; pp += 2) {
        {
            float pj = psh[pair0 + pp];
            unsigned int pb = __float_as_uint(pj);
            unsigned long long pk, ww;
            asm("mov.b64 %0, {%1, %1};" : "=l"(pk) : "r"(pb));
            ww = __ldg(wbase + (size_t)(pair0 + pp) * 32);
            asm("fma.rn.f32x2 %0, %1, %2, %0;" : "+l"(accA) : "l"(pk), "l"(ww));
        }
        {
            float pj = psh[pair0 + pp + 1];
            unsigned int pb = __float_as_uint(pj);
            unsigned long long pk, ww;
            asm("mov.b64 %0, {%1, %1};" : "=l"(pk) : "r"(pb));
            ww = __ldg(wbase + (size_t)(pair0 + pp + 1) * 32);
            asm("fma.rn.f32x2 %0, %1, %2, %0;" : "+l"(accB) : "l"(pk), "l"(ww));
        }
    }
    unsigned long long accW;
    asm("add.rn.f32x2 %0, %1, %2;" : "=l"(accW) : "l"(accA), "l"(accB));
    sacc[wid][lane] = accW;
    __syncthreads();

    // ---- warp 0 combines 4 partials and finishes ----
    if (tid < 32) {
        unsigned long long t01, t23, tt;
        asm("add.rn.f32x2 %0, %1, %2;" : "=l"(t01) : "l"(sacc[0][tid]), "l"(sacc[1][tid]));
        asm("add.rn.f32x2 %0, %1, %2;" : "=l"(t23) : "l"(sacc[2][tid]), "l"(sacc[3][tid]));
        asm("add.rn.f32x2 %0, %1, %2;" : "=l"(tt)  : "l"(t01), "l"(t23));
        unsigned int u0, u1;
        asm("mov.b64 {%0, %1}, %2;" : "=r"(u0), "=r"(u1) : "l"(tt));
        float phi0 = tanhf(__uint_as_float(u0));
        float phi1 = tanhf(__uint_as_float(u1));
        int o0 = 2 * tid, o1 = 2 * tid + 1;
        float c0 = phi0 * Wout[o0 * 2 + 0] + phi1 * Wout[o1 * 2 + 0];
        float c1 = phi0 * Wout[o0 * 2 + 1] + phi1 * Wout[o1 * 2 + 1];
        #pragma unroll
        for (int s = 16; s > 0; s >>= 1) {
            c0 += __shfl_xor_sync(0xffffffffu, c0, s);
            c1 += __shfl_xor_sync(0xffffffffu, c1, s);
        }
        if (tid == 0)
            g_table[g] = make_float2(c0, c1);
    }
}

// ---------------------------------------------------------------------------
// Kernel 2: per-batch 4-point cubic Lagrange interpolation (compact x)
// ---------------------------------------------------------------------------
__global__ void __launch_bounds__(256) k_apply(float* __restrict__ out) {
    __shared__ float s_lo, s_h;
    reduce_range(threadIdx.x, &s_lo, &s_h);
    __syncthreads();

    int b = blockIdx.x * blockDim.x + threadIdx.x;
    float xv = g_xlast[b];

    float t = (xv - s_lo) / s_h + 1.5f;
    int i0 = (int)floorf(t);
    i0 = max(1, min(GTAB - 3, i0));
    float u = t - (float)i0;

    float um1 = u - 1.f, um2 = u - 2.f, up1 = u + 1.f;
    float wA = -u * um1 * um2 * (1.f / 6.f);
    float wB =  up1 * um1 * um2 * 0.5f;
    float wC = -up1 * u * um2 * 0.5f;
    float wD =  up1 * u * um1 * (1.f / 6.f);

    float2 fA = g_table[i0 - 1];
    float2 fB = g_table[i0];
    float2 fC = g_table[i0 + 1];
    float2 fD = g_table[i0 + 2];

    float o0 = wA * fA.x + wB * fB.x + wC * fC.x + wD * fD.x;
    float o1 = wA * fA.y + wB * fB.y + wC * fC.y + wD * fD.y;
    reinterpret_cast<float2*>(out)[b] = make_float2(o0, o1);
}

// ---------------------------------------------------------------------------
extern "C" void kernel_launch(void* const* d_in, const int* in_sizes, int n_in,
                              void* d_out, int out_size) {
    const float* x    = (const float*)d_in[0];
    const float* Wx   = (const float*)d_in[1];
    const float* ax   = (const float*)d_in[2];
    const float* cx   = (const float*)d_in[3];
    // d_in[4..6] = Wh, ah, ch -- mathematically unused by the reference
    const float* Wc   = (const float*)d_in[7];
    const float* ac   = (const float*)d_in[8];
    const float* cc   = (const float*)d_in[9];
    const float* Wout = (const float*)d_in[10];

    k_pre  <<<NPART, 128>>>(x, Wc);
    k_table<<<GTAB, 128>>>(Wx, ax, cx, ac, cc, Wout);
    k_apply<<<BATCH / 256, 256>>>((float*)d_out);
}

// round 4
// speedup vs baseline: 2.2876x; 1.0897x over previous
#include <cuda_runtime.h>
#include <math.h>

#define HIDDEN     64
#define NBASIS     10
#define SEQ        96
#define BATCH      16384
#define NPAIR      (HIDDEN * NBASIS)   // 640
#define GTAB       128
#define GPTS       4                   // grid points per table block
#define ABLK       (GTAB / GPTS)       // 32 table blocks
#define PAIRS_PW   (NPAIR / 4)         // 160 pairs per warp

#define DOM_LO     (-6.0f)
#define DOM_H      (12.0f / (float)(GTAB - 4))   // step
#define DOM_INVH   ((float)(GTAB - 4) / 12.0f)

__device__ __align__(16) float g_Wct[NPAIR * HIDDEN];  // [pair][o], 160KB
__device__ float2 g_table[GTAB];

// ---------------------------------------------------------------------------
// Kernel T: transpose Wc[i][o][k] -> g_Wct[(i*10+k)*64 + o]
// grid = 160 x 256, one element per thread (coalesced read, scattered write)
// ---------------------------------------------------------------------------
__global__ void __launch_bounds__(256) k_tr(const float* __restrict__ Wc) {
    int gi = blockIdx.x * 256 + threadIdx.x;       // 40960 exact
    int i   = gi / (HIDDEN * NBASIS);
    int rem = gi - i * (HIDDEN * NBASIS);
    int o   = rem / NBASIS;
    int k   = rem - o * NBASIS;
    g_Wct[(i * NBASIS + k) * HIDDEN + o] = Wc[gi];
}

// ---------------------------------------------------------------------------
// Kernel A: tabulate F at GTAB points, GPTS points per block.
// grid = 32 blocks x 128 threads
// ---------------------------------------------------------------------------
__global__ void __launch_bounds__(128) k_table(
    const float* __restrict__ Wx,  const float* __restrict__ ax,
    const float* __restrict__ cx,  const float* __restrict__ ac,
    const float* __restrict__ cc,  const float* __restrict__ Wout)
{
    __shared__ __align__(16) float hsh[GPTS][HIDDEN];   // 1 KB
    __shared__ __align__(16) float psh[GPTS][NPAIR];    // 10 KB
    __shared__ __align__(16) float sf[GPTS][4][128];    // 8 KB
    __shared__ float phs[GPTS][HIDDEN];                 // 1 KB

    const int tid    = threadIdx.x;
    const int wid    = tid >> 5;
    const int lane   = tid & 31;
    const int lane16 = lane & 15;
    const int sel    = lane >> 4;          // 0: even pairs, 1: odd pairs
    const int g0     = blockIdx.x * GPTS;

    // ---- stage 1: h[pt][64] ----
    {
        const int o    = tid & 63;
        const int half = tid >> 6;
        #pragma unroll
        for (int j = 0; j < 2; j++) {
            int pt = 2 * j + half;
            float xg = DOM_LO + ((float)(g0 + pt) - 1.5f) * DOM_H;
            float s = 0.f;
            #pragma unroll
            for (int k = 0; k < NBASIS; k++) {
                float t = tanhf(xg * ax[k] + cx[k]);
                s += t * Wx[o * NBASIS + k];
            }
            hsh[pt][o] = tanhf(s);
        }
    }
    __syncthreads();

    // ---- stage 2: p[pt][640] = tanh(h[pt][i]*ac + cc) ----
    #pragma unroll
    for (int j = 0; j < NPAIR / 128; j++) {
        int pair = j * 128 + tid;
        int i    = pair / NBASIS;
        float a = ac[pair], c = cc[pair];
        #pragma unroll
        for (int pt = 0; pt < GPTS; pt++)
            psh[pt][pair] = tanhf(hsh[pt][i] * a + c);
    }
    __syncthreads();

    // ---- stage 3: per-warp 160-pair reduction, 4 outputs per lane16 ----
    // lane16 owns o = 4*lane16 .. 4*lane16+3; sel splits even/odd pairs.
    unsigned long long acc0[GPTS], acc1[GPTS];
    #pragma unroll
    for (int pt = 0; pt < GPTS; pt++) { acc0[pt] = 0ull; acc1[pt] = 0ull; }

    const int pair0 = wid * PAIRS_PW;
    const ulonglong2* wb = reinterpret_cast<const ulonglong2*>(g_Wct);

    #pragma unroll 10
    for (int it = 0; it < PAIRS_PW; it += 2) {
        int pair = pair0 + it + sel;
        ulonglong2 w = __ldg(wb + (size_t)pair * 16 + lane16);
        #pragma unroll
        for (int pt = 0; pt < GPTS; pt++) {
            float pj = psh[pt][pair];
            unsigned int pb = __float_as_uint(pj);
            unsigned long long pk;
            asm("mov.b64 %0, {%1, %1};" : "=l"(pk) : "r"(pb));
            asm("fma.rn.f32x2 %0, %1, %2, %0;" : "+l"(acc0[pt]) : "l"(pk), "l"(w.x));
            asm("fma.rn.f32x2 %0, %1, %2, %0;" : "+l"(acc1[pt]) : "l"(pk), "l"(w.y));
        }
    }

    // stash partials: sf[pt][wid][sel*64 + 4*lane16 .. +3]
    #pragma unroll
    for (int pt = 0; pt < GPTS; pt++) {
        unsigned long long* dst = reinterpret_cast<unsigned long long*>(
            &sf[pt][wid][sel * 64 + 4 * lane16]);
        dst[0] = acc0[pt];
        dst[1] = acc1[pt];
    }
    __syncthreads();

    // ---- combine 8 partials per output, tanh ----
    if (tid < HIDDEN) {
        #pragma unroll
        for (int pt = 0; pt < GPTS; pt++) {
            float tot = 0.f;
            #pragma unroll
            for (int w = 0; w < 4; w++)
                tot += sf[pt][w][tid] + sf[pt][w][tid + 64];
            phs[pt][tid] = tanhf(tot);
        }
    }
    __syncthreads();

    // ---- head: warp 0, o = 2*tid, 2*tid+1 ----
    if (tid < 32) {
        float4 wv = __ldg(reinterpret_cast<const float4*>(Wout) + tid);
        #pragma unroll
        for (int pt = 0; pt < GPTS; pt++) {
            float phi0 = phs[pt][2 * tid];
            float phi1 = phs[pt][2 * tid + 1];
            float c0 = phi0 * wv.x + phi1 * wv.z;
            float c1 = phi0 * wv.y + phi1 * wv.w;
            #pragma unroll
            for (int s = 16; s > 0; s >>= 1) {
                c0 += __shfl_xor_sync(0xffffffffu, c0, s);
                c1 += __shfl_xor_sync(0xffffffffu, c1, s);
            }
            if (tid == 0)
                g_table[g0 + pt] = make_float2(c0, c1);
        }
    }
}

// ---------------------------------------------------------------------------
// Kernel B: cubic Lagrange interpolation, 2 batch elements per thread
// grid = 64 blocks x 128 threads
// ---------------------------------------------------------------------------
__device__ __forceinline__ float2 interp(float xv) {
    float t = (xv - DOM_LO) * DOM_INVH + 1.5f;
    int i0 = (int)floorf(t);
    i0 = max(1, min(GTAB - 3, i0));
    float u = t - (float)i0;

    float um1 = u - 1.f, um2 = u - 2.f, up1 = u + 1.f;
    float wA = -u * um1 * um2 * (1.f / 6.f);
    float wB =  up1 * um1 * um2 * 0.5f;
    float wC = -up1 * u * um2 * 0.5f;
    float wD =  up1 * u * um1 * (1.f / 6.f);

    float2 fA = g_table[i0 - 1];
    float2 fB = g_table[i0];
    float2 fC = g_table[i0 + 1];
    float2 fD = g_table[i0 + 2];

    return make_float2(wA * fA.x + wB * fB.x + wC * fC.x + wD * fD.x,
                       wA * fA.y + wB * fB.y + wC * fC.y + wD * fD.y);
}

__global__ void __launch_bounds__(128) k_apply(const float* __restrict__ x,
                                               float* __restrict__ out) {
    int b0 = blockIdx.x * 128 + threadIdx.x;      // [0, 8192)
    int b1 = b0 + 8192;
    float xv0 = x[b0 * SEQ + (SEQ - 1)];
    float xv1 = x[b1 * SEQ + (SEQ - 1)];
    float2 r0 = interp(xv0);
    float2 r1 = interp(xv1);
    reinterpret_cast<float2*>(out)[b0] = r0;
    reinterpret_cast<float2*>(out)[b1] = r1;
}

// ---------------------------------------------------------------------------
extern "C" void kernel_launch(void* const* d_in, const int* in_sizes, int n_in,
                              void* d_out, int out_size) {
    const float* x    = (const float*)d_in[0];
    const float* Wx   = (const float*)d_in[1];
    const float* ax   = (const float*)d_in[2];
    const float* cx   = (const float*)d_in[3];
    // d_in[4..6] = Wh, ah, ch -- mathematically unused by the reference
    const float* Wc   = (const float*)d_in[7];
    const float* ac   = (const float*)d_in[8];
    const float* cc   = (const float*)d_in[9];
    const float* Wout = (const float*)d_in[10];

    k_tr   <<<(NPAIR * HIDDEN) / 256, 256>>>(Wc);
    k_table<<<ABLK, 128>>>(Wx, ax, cx, ac, cc, Wout);
    k_apply<<<BATCH / 256, 128>>>(x, (float*)d_out);
}